// round 1
// baseline (speedup 1.0000x reference)
#include <cuda_runtime.h>
#include <cuda_bf16.h>
#include <cstdint>

// Problem constants (fixed by the reference)
#define NT      131072
#define HID     2048
#define NRANKS  8
#define NEXP    16
#define NSEG    128            // NRANKS * NEXP
#define VEC     (HID / 4)      // 512 float4 per row

// Scratch (no device allocation allowed -> __device__ globals)
__device__ int g_base_in[NSEG];   // input-row base for each output segment
__device__ int g_out_off[NSEG + 1]; // exclusive cumsum of output segment sizes

// -------------------------------------------------------------------------
// Setup: compute segment offset tables + expert_token_num tail of output.
// counts layout: counts[r * NEXP + e], rank-major (input order).
// Output segment order: p = e * NRANKS + r (expert-major, rank-minor).
// -------------------------------------------------------------------------
__global__ void moe_setup_kernel(const int* __restrict__ counts,
                                 float* __restrict__ out,
                                 long long out_elems) {
    __shared__ int sc[NSEG];
    if (threadIdx.x < NSEG) sc[threadIdx.x] = counts[threadIdx.x];
    __syncthreads();

    if (threadIdx.x == 0) {
        // exclusive cumsum over input segments (input is contiguous in seg order)
        int in_off[NSEG + 1];
        in_off[0] = 0;
        #pragma unroll 4
        for (int s = 0; s < NSEG; s++) in_off[s + 1] = in_off[s] + sc[s];

        // output segments in (expert, rank) order
        int acc = 0;
        for (int p = 0; p < NSEG; p++) {
            int e = p >> 3;          // p / NRANKS  (NRANKS == 8)
            int r = p & 7;           // p % NRANKS
            int inseg = r * NEXP + e;
            g_base_in[p] = in_off[inseg];
            g_out_off[p] = acc;
            acc += sc[inseg];
        }
        g_out_off[NSEG] = acc;       // == NT
    }
    __syncthreads();

    // expert_token_num[e] = sum over ranks; written as float to output tail
    if (threadIdx.x < NEXP) {
        int e = threadIdx.x;
        int s = 0;
        #pragma unroll
        for (int r = 0; r < NRANKS; r++) s += sc[r * NEXP + e];
        long long pos = (long long)NT * HID + 2LL * NT + e;
        if (pos < out_elems) out[pos] = (float)s;
    }
}

// -------------------------------------------------------------------------
// Gather: one block per output row. 256 threads, 2x float4 each (8 KB row).
// Streaming loads/stores (working set 2 GiB >> L2).
// -------------------------------------------------------------------------
__global__ __launch_bounds__(256, 8)
void moe_gather_kernel(const float4* __restrict__ tokens,
                       const float* __restrict__ scales,
                       float* __restrict__ out,
                       long long out_elems) {
    __shared__ int s_src;
    const int row = blockIdx.x;

    if (threadIdx.x == 0) {
        // binary search: largest p with g_out_off[p] <= row
        int lo = 0, hi = NSEG - 1;
        #pragma unroll
        for (int it = 0; it < 7; it++) {
            int mid = (lo + hi + 1) >> 1;
            if (g_out_off[mid] <= row) lo = mid; else hi = mid - 1;
        }
        int src = g_base_in[lo] + (row - g_out_off[lo]);
        s_src = src;

        const long long NH = (long long)NT * HID;
        long long spos = NH + row;           // permuted scales
        long long ipos = NH + NT + row;      // idx (as float; < 2^24, exact)
        if (spos < out_elems) out[spos] = scales[src];
        if (ipos < out_elems) out[ipos] = (float)src;
    }
    __syncthreads();

    const int src = s_src;
    const float4* __restrict__ in = tokens + (long long)src * VEC;
    float4* __restrict__ o = reinterpret_cast<float4*>(out) + (long long)row * VEC;

    const int t = threadIdx.x;
    // 512 float4 per row / 256 threads = 2 each; keep both loads in flight (MLP)
    float4 a = __ldcs(in + t);
    float4 b = __ldcs(in + t + 256);
    __stcs(o + t, a);
    __stcs(o + t + 256, b);
}

extern "C" void kernel_launch(void* const* d_in, const int* in_sizes, int n_in,
                              void* d_out, int out_size) {
    const float* tokens = (const float*)d_in[0];
    const int*   counts = (const int*)d_in[1];   // [NRANKS, NEXP]
    const float* scales = (const float*)d_in[2];
    // d_in[3] = expert_token_num_type (==1, counts), d_in[4] = idx_type (==0): fixed semantics
    float* out = (float*)d_out;
    const long long out_elems = (long long)out_size;

    moe_setup_kernel<<<1, 128>>>(counts, out, out_elems);
    moe_gather_kernel<<<NT, 256>>>((const float4*)tokens, scales, out, out_elems);
}